// round 3
// baseline (speedup 1.0000x reference)
#include <cuda_runtime.h>
#include <cuda_bf16.h>
#include <cstdint>

// ============================================================================
// Problem constants
// ============================================================================
#define NTOK   8192
#define NROW   65536          // NTOK * 8 blades
#define DB     256            // blade dim (= GEMM1 K)
#define DF     1024           // FFN dim

// ============================================================================
// Scratch (static __device__ — no allocation)
// ============================================================================
__device__ __align__(16) __nv_bfloat16 g_flat[(size_t)NROW * DB];   // 32MB, LN output
__device__ __align__(16) __nv_bfloat16 g_h[(size_t)NROW * DF];      // 128MB, swiglu output
// W1: gate/up interleaved in 8-row groups: rows 16q+0..7 = gate n=8q..8q+7,
//     rows 16q+8..15 = up (same n). [2048 rows][256 k]
__device__ __align__(16) __nv_bfloat16 g_B1[2u * DF * DB];
__device__ __align__(16) __nv_bfloat16 g_B2[(size_t)DB * DF];       // Wd^T: [n=256][k=1024]

// ============================================================================
// PTX helpers (sm_90-class only — NO tcgen05; ptxas target is plain sm_103)
// ============================================================================
__device__ __forceinline__ uint32_t smem_to_u32(const void* p) {
    uint32_t a;
    asm("{ .reg .u64 t; cvta.to.shared.u64 t, %1; cvt.u32.u64 %0, t; }" : "=r"(a) : "l"(p));
    return a;
}

#define CP_ASYNC16(dst_u32, src_ptr) \
    asm volatile("cp.async.cg.shared.global [%0], [%1], 16;" :: "r"(dst_u32), "l"(src_ptr))
#define CP_COMMIT() asm volatile("cp.async.commit_group;" ::: "memory")
#define CP_WAIT(n)  asm volatile("cp.async.wait_group %0;" :: "n"(n) : "memory")

#define LDSM_X4(r, addr) \
    asm volatile("ldmatrix.sync.aligned.m8n8.x4.shared.b16 {%0,%1,%2,%3}, [%4];" \
        : "=r"((r)[0]), "=r"((r)[1]), "=r"((r)[2]), "=r"((r)[3]) : "r"(addr))

#define MMA16816(c, a, b0, b1) \
    asm volatile("mma.sync.aligned.m16n8k16.row.col.f32.bf16.bf16.f32 " \
        "{%0,%1,%2,%3}, {%4,%5,%6,%7}, {%8,%9}, {%0,%1,%2,%3};" \
        : "+f"((c)[0]), "+f"((c)[1]), "+f"((c)[2]), "+f"((c)[3]) \
        : "r"((a)[0]), "r"((a)[1]), "r"((a)[2]), "r"((a)[3]), "r"(b0), "r"(b1))

// SW128-style byte swizzle (Swizzle<3,4,3>): conflict-free ldmatrix on 128B rows
__device__ __forceinline__ uint32_t swz(uint32_t off) {
    return off ^ ((off >> 3) & 0x70);
}

// ============================================================================
// Kernel W: weight prep (transpose to [n][k] bf16; W1 gate/up interleaved)
// ============================================================================
__global__ void kPrep(const float* __restrict__ Wg, const float* __restrict__ Wu,
                      const float* __restrict__ Wd) {
    int i = blockIdx.x * 256 + threadIdx.x;   // grid 3072 -> 786432
    if (i < 262144) {                         // gate: n in [0,1024), k in [0,256)
        int n = i >> 8, k = i & 255;
        int row = (n >> 3) * 16 + (n & 7);
        g_B1[(size_t)row * 256 + k] = __float2bfloat16(Wg[k * 1024 + n]);
    } else if (i < 524288) {                  // up
        int j = i - 262144;
        int n = j >> 8, k = j & 255;
        int row = (n >> 3) * 16 + 8 + (n & 7);
        g_B1[(size_t)row * 256 + k] = __float2bfloat16(Wu[k * 1024 + n]);
    } else {                                  // down: [n=256][k=1024]
        int j = i - 524288;
        int n = j >> 10, k = j & 1023;
        g_B2[j] = __float2bfloat16(Wd[k * 256 + n]);
    }
}

// ============================================================================
// Kernel A: geometric product + gate mix + LayerNorm -> g_flat (bf16)
// ============================================================================
__device__ __constant__ float c_sg[64] = {
    1, 1, 1, 1, 1, 1, 1, 1,
    1, 1, 1, 1, 1, 1, 1, 1,
    1,-1, 1, 1,-1,-1, 1,-1,
    1,-1,-1, 1, 1,-1,-1, 1,
    1,-1, 1, 1,-1,-1, 1,-1,
    1,-1,-1, 1, 1,-1,-1, 1,
    1, 1,-1, 1,-1, 1,-1,-1,
    1, 1,-1, 1,-1, 1,-1,-1};

__global__ void __launch_bounds__(256) kA(const float* __restrict__ x,
                                          const float* __restrict__ iw,
                                          const float* __restrict__ gg,
                                          const float* __restrict__ lnw,
                                          const float* __restrict__ lnb) {
    __shared__ float xs[8 * 256];
    __shared__ float cf[64];
    int tok = blockIdx.x, t = threadIdx.x;

    const float4* xsrc = (const float4*)(x + (size_t)tok * 2048);
    float4* xd = (float4*)xs;
    xd[t]       = xsrc[t];
    xd[t + 256] = xsrc[t + 256];
    if (t < 64) cf[t] = c_sg[t] / (1.f + __expf(-iw[t]));
    __syncthreads();

    float g = 1.f / (1.f + __expf(-gg[0]));
    float xr[8];
#pragma unroll
    for (int b = 0; b < 8; b++) xr[b] = xs[b * 256 + t];

    // Cayley targets (Cl(3)) — hand-verified vs reference _derive_cayley_table
    constexpr int KTK[64] = {
        0,1,2,3,4,5,6,7,
        1,0,4,5,2,3,7,6,
        2,4,0,6,1,7,3,5,
        3,5,6,0,7,1,2,4,
        4,2,1,7,0,6,5,3,
        5,3,7,1,6,0,4,2,
        6,7,3,2,5,4,0,1,
        7,6,5,4,3,2,1,0};

    float geo[8] = {0, 0, 0, 0, 0, 0, 0, 0};
#pragma unroll
    for (int p = 0; p < 64; p++)
        geo[KTK[p]] += cf[p] * xr[p >> 3] * xr[p & 7];

#pragma unroll
    for (int b = 0; b < 8; b++)
        xs[b * 256 + t] = g * geo[b] + (1.f - g) * xr[b];
    __syncthreads();

    // LayerNorm: warp w handles blade b = w
    int w = t >> 5, lane = t & 31;
    float v[8], s = 0.f, sq = 0.f;
#pragma unroll
    for (int j = 0; j < 8; j++) {
        v[j] = xs[w * 256 + lane + 32 * j];
        s += v[j]; sq += v[j] * v[j];
    }
#pragma unroll
    for (int o = 16; o > 0; o >>= 1) {
        s  += __shfl_xor_sync(0xFFFFFFFFu, s, o);
        sq += __shfl_xor_sync(0xFFFFFFFFu, sq, o);
    }
    float mu   = s * (1.f / 256.f);
    float var  = fmaxf(sq * (1.f / 256.f) - mu * mu, 0.f);
    float rstd = rsqrtf(var + 1e-5f);

    size_t row = (size_t)tok * 8 + w;
    __nv_bfloat16* dst = g_flat + row * 256;
#pragma unroll
    for (int j = 0; j < 8; j++) {
        int col = lane + 32 * j;
        dst[col] = __float2bfloat16((v[j] - mu) * rstd * lnw[col] + lnb[col]);
    }
}

// ============================================================================
// HMMA GEMM common: CTA 128(M) x 256(N-rows of B), 8 warps (2M x 4N),
// warp tile 64x64, K-chunk 64, 2-stage cp.async pipeline.
// smem: A stages @ 0/16K (16KB each), B stages @ 32K/64K (32KB each) = 96KB.
// ============================================================================
static constexpr int G_SMEM_BYTES = 98304;

struct Frag { uint32_t a[4][4]; uint32_t b[4][4]; };

// compute one K=64 chunk: c[4][8][4] accumulators
__device__ __forceinline__ void compute_chunk(uint32_t sA, uint32_t sB,
                                              int wm, int wn, int lane,
                                              float c[4][8][4]) {
#pragma unroll
    for (int ks = 0; ks < 4; ks++) {
        uint32_t a[4][4], b[4][4];
        int kb = ks * 32;                       // byte offset of k within 128B row
        int acol = (lane >> 4) * 16 + kb;       // 0/16 + kb
#pragma unroll
        for (int mt = 0; mt < 4; mt++) {
            uint32_t row = wm * 64 + mt * 16 + (lane & 15);
            LDSM_X4(a[mt], sA + swz(row * 128 + acol));
        }
        int bcol = ((lane >> 3) & 1) * 16 + kb;
#pragma unroll
        for (int p = 0; p < 4; p++) {
            uint32_t row = wn * 64 + p * 16 + (lane & 7) + ((lane >> 4) << 3);
            LDSM_X4(b[p], sB + swz(row * 128 + bcol));
        }
#pragma unroll
        for (int mt = 0; mt < 4; mt++)
#pragma unroll
            for (int nt = 0; nt < 8; nt++)
                MMA16816(c[mt][nt], a[mt], b[nt >> 1][(nt & 1) * 2], b[nt >> 1][(nt & 1) * 2 + 1]);
    }
}

// stage loader: A 128 rows x 64 bf16, B 256 rows x 64 bf16 (K-chunk kc)
__device__ __forceinline__ void load_chunk(uint32_t sA, uint32_t sB,
                                           const __nv_bfloat16* gA, int a_stride,
                                           const __nv_bfloat16* gB, int b_stride,
                                           int m0, int nb0, int k0, int t) {
#pragma unroll
    for (int i = 0; i < 4; i++) {               // A: 1024 x 16B
        int u = t + i * 256;
        int r = u >> 3, cu = u & 7;
        CP_ASYNC16(sA + swz((uint32_t)r * 128 + cu * 16),
                   gA + (size_t)(m0 + r) * a_stride + k0 + cu * 8);
    }
#pragma unroll
    for (int i = 0; i < 8; i++) {               // B: 2048 x 16B
        int u = t + i * 256;
        int r = u >> 3, cu = u & 7;
        CP_ASYNC16(sB + swz((uint32_t)r * 128 + cu * 16),
                   gB + (size_t)(nb0 + r) * b_stride + k0 + cu * 8);
    }
}

// ============================================================================
// GEMM1: g_flat[65536,256] @ g_B1 (gate/up interleaved) -> swiglu -> g_h
// grid (512, 8): blockIdx.y covers 256 B-rows = 128 FFN cols
// ============================================================================
__global__ void __launch_bounds__(256, 1) kGemm1() {
    extern __shared__ __align__(1024) char smem[];
    uint32_t sb = smem_to_u32(smem);
    int t = threadIdx.x, lane = t & 31, wid = t >> 5;
    int wm = wid & 1, wn = wid >> 1;
    int m0 = blockIdx.x * 128, nb0 = blockIdx.y * 256;

    float c[4][8][4] = {};
    load_chunk(sb, sb + 32768, g_flat, 256, g_B1, 256, m0, nb0, 0, t);
    CP_COMMIT();

#pragma unroll
    for (int kc = 0; kc < 4; kc++) {
        uint32_t sA = sb + (kc & 1) * 16384;
        uint32_t sB = sb + 32768 + (kc & 1) * 32768;
        if (kc + 1 < 4) {
            load_chunk(sb + ((kc + 1) & 1) * 16384, sb + 32768 + ((kc + 1) & 1) * 32768,
                       g_flat, 256, g_B1, 256, m0, nb0, (kc + 1) * 64, t);
            CP_COMMIT();
            CP_WAIT(1);
        } else {
            CP_WAIT(0);
        }
        __syncthreads();
        compute_chunk(sA, sB, wm, wn, lane, c);
        __syncthreads();
    }

    // epilogue: ntile 2q = gate, 2q+1 = up (same FFN cols) -> silu(g)*u, bf16
    int ncolw = blockIdx.y * 128 + wn * 32;
#pragma unroll
    for (int mt = 0; mt < 4; mt++) {
        int r0 = m0 + wm * 64 + mt * 16 + (lane >> 2);
#pragma unroll
        for (int q = 0; q < 4; q++) {
            float* cg = c[mt][2 * q];
            float* cu = c[mt][2 * q + 1];
            int ncol = ncolw + q * 8 + (lane & 3) * 2;
#pragma unroll
            for (int half = 0; half < 2; half++) {
                float zg0 = cg[half * 2], zg1 = cg[half * 2 + 1];
                float zu0 = cu[half * 2], zu1 = cu[half * 2 + 1];
                __nv_bfloat162 pk;
                pk.x = __float2bfloat16(zg0 / (1.f + __expf(-zg0)) * zu0);
                pk.y = __float2bfloat16(zg1 / (1.f + __expf(-zg1)) * zu1);
                *(__nv_bfloat162*)(g_h + (size_t)(r0 + half * 8) * 1024 + ncol) = pk;
            }
        }
    }
}

// ============================================================================
// GEMM2: g_h[65536,1024] @ g_B2[256,1024] -> + x residual -> out fp32
// grid (512): CTA covers full N=256, K in 16 chunks of 64
// ============================================================================
__global__ void __launch_bounds__(256, 1)
kGemm2(const float* __restrict__ x, float* __restrict__ out) {
    extern __shared__ __align__(1024) char smem[];
    uint32_t sb = smem_to_u32(smem);
    int t = threadIdx.x, lane = t & 31, wid = t >> 5;
    int wm = wid & 1, wn = wid >> 1;
    int m0 = blockIdx.x * 128;

    float c[4][8][4] = {};
    load_chunk(sb, sb + 32768, g_h, 1024, g_B2, 1024, m0, 0, 0, t);
    CP_COMMIT();

    for (int kc = 0; kc < 16; kc++) {
        uint32_t sA = sb + (kc & 1) * 16384;
        uint32_t sB = sb + 32768 + (kc & 1) * 32768;
        if (kc + 1 < 16) {
            load_chunk(sb + ((kc + 1) & 1) * 16384, sb + 32768 + ((kc + 1) & 1) * 32768,
                       g_h, 1024, g_B2, 1024, m0, 0, (kc + 1) * 64, t);
            CP_COMMIT();
            CP_WAIT(1);
        } else {
            CP_WAIT(0);
        }
        __syncthreads();
        compute_chunk(sA, sB, wm, wn, lane, c);
        __syncthreads();
    }

    // epilogue: fp32 residual add
#pragma unroll
    for (int mt = 0; mt < 4; mt++) {
        int r0 = m0 + wm * 64 + mt * 16 + (lane >> 2);
#pragma unroll
        for (int nt = 0; nt < 8; nt++) {
            int col = wn * 64 + nt * 8 + (lane & 3) * 2;
#pragma unroll
            for (int half = 0; half < 2; half++) {
                size_t idx = (size_t)(r0 + half * 8) * 256 + col;
                float2 xv = *(const float2*)(x + idx);
                float2 ov;
                ov.x = xv.x + c[mt][nt][half * 2];
                ov.y = xv.y + c[mt][nt][half * 2 + 1];
                *(float2*)(out + idx) = ov;
            }
        }
    }
}

// ============================================================================
// Launch
// ============================================================================
extern "C" void kernel_launch(void* const* d_in, const int* in_sizes, int n_in,
                              void* d_out, int out_size) {
    (void)in_sizes; (void)n_in; (void)out_size;
    const float* x   = (const float*)d_in[0];
    const float* iw  = (const float*)d_in[1];
    const float* gg  = (const float*)d_in[2];
    const float* lnw = (const float*)d_in[3];
    const float* lnb = (const float*)d_in[4];
    const float* Wg  = (const float*)d_in[5];
    const float* Wu  = (const float*)d_in[6];
    const float* Wd  = (const float*)d_in[7];
    float* out = (float*)d_out;

    cudaFuncSetAttribute(kGemm1, cudaFuncAttributeMaxDynamicSharedMemorySize, G_SMEM_BYTES);
    cudaFuncSetAttribute(kGemm2, cudaFuncAttributeMaxDynamicSharedMemorySize, G_SMEM_BYTES);

    kPrep<<<3072, 256>>>(Wg, Wu, Wd);
    kA<<<NTOK, 256>>>(x, iw, gg, lnw, lnb);
    kGemm1<<<dim3(NROW / 128, DF * 2 / 256), 256, G_SMEM_BYTES>>>();
    kGemm2<<<NROW / 128, 256, G_SMEM_BYTES>>>(x, out);
}

// round 5
// speedup vs baseline: 1.2702x; 1.2702x over previous
#include <cuda_runtime.h>
#include <cuda_bf16.h>
#include <cstdint>

// ============================================================================
// Problem constants
// ============================================================================
#define NTOK   8192
#define NROW   65536          // NTOK * 8 blades
#define DB     256            // blade dim (= GEMM1 K)
#define DF     1024           // FFN dim

// ============================================================================
// Scratch (static __device__ — no allocation)
// ============================================================================
__device__ __align__(16) __nv_bfloat16 g_flat[(size_t)NROW * DB];   // 32MB, LN output
__device__ __align__(16) __nv_bfloat16 g_h[(size_t)NROW * DF];      // 128MB, swiglu output
// W1: gate/up interleaved in 8-row groups: rows 16q+0..7 = gate n=8q..8q+7,
//     rows 16q+8..15 = up (same n). [2048 rows][256 k]
__device__ __align__(16) __nv_bfloat16 g_B1[2u * DF * DB];
__device__ __align__(16) __nv_bfloat16 g_B2[(size_t)DB * DF];       // Wd^T: [n=256][k=1024]

// ============================================================================
// PTX helpers (sm_90-class only — NO tcgen05; ptxas target is plain sm_103)
// ============================================================================
__device__ __forceinline__ uint32_t smem_to_u32(const void* p) {
    uint32_t a;
    asm("{ .reg .u64 t; cvta.to.shared.u64 t, %1; cvt.u32.u64 %0, t; }" : "=r"(a) : "l"(p));
    return a;
}

#define CP_ASYNC16(dst_u32, src_ptr) \
    asm volatile("cp.async.cg.shared.global [%0], [%1], 16;" :: "r"(dst_u32), "l"(src_ptr))
#define CP_COMMIT() asm volatile("cp.async.commit_group;" ::: "memory")
#define CP_WAIT(n)  asm volatile("cp.async.wait_group %0;" :: "n"(n) : "memory")

#define LDSM_X4(r, addr) \
    asm volatile("ldmatrix.sync.aligned.m8n8.x4.shared.b16 {%0,%1,%2,%3}, [%4];" \
        : "=r"((r)[0]), "=r"((r)[1]), "=r"((r)[2]), "=r"((r)[3]) : "r"(addr))

#define MMA16816(c, a, b0, b1) \
    asm volatile("mma.sync.aligned.m16n8k16.row.col.f32.bf16.bf16.f32 " \
        "{%0,%1,%2,%3}, {%4,%5,%6,%7}, {%8,%9}, {%0,%1,%2,%3};" \
        : "+f"((c)[0]), "+f"((c)[1]), "+f"((c)[2]), "+f"((c)[3]) \
        : "r"((a)[0]), "r"((a)[1]), "r"((a)[2]), "r"((a)[3]), "r"(b0), "r"(b1))

// SW128-style byte swizzle (Swizzle<3,4,3>): conflict-free ldmatrix on 128B rows
__device__ __forceinline__ uint32_t swz(uint32_t off) {
    return off ^ ((off >> 3) & 0x70);
}

// ============================================================================
// Kernel W: weight prep (transpose to [n][k] bf16; W1 gate/up interleaved)
// ============================================================================
__global__ void kPrep(const float* __restrict__ Wg, const float* __restrict__ Wu,
                      const float* __restrict__ Wd) {
    int i = blockIdx.x * 256 + threadIdx.x;   // grid 3072 -> 786432
    if (i < 262144) {                         // gate: n in [0,1024), k in [0,256)
        int n = i >> 8, k = i & 255;
        int row = (n >> 3) * 16 + (n & 7);
        g_B1[(size_t)row * 256 + k] = __float2bfloat16(Wg[k * 1024 + n]);
    } else if (i < 524288) {                  // up
        int j = i - 262144;
        int n = j >> 8, k = j & 255;
        int row = (n >> 3) * 16 + 8 + (n & 7);
        g_B1[(size_t)row * 256 + k] = __float2bfloat16(Wu[k * 1024 + n]);
    } else {                                  // down: [n=256][k=1024]
        int j = i - 524288;
        int n = j >> 10, k = j & 1023;
        g_B2[j] = __float2bfloat16(Wd[k * 256 + n]);
    }
}

// ============================================================================
// Kernel A: geometric product + gate mix + LayerNorm -> g_flat (bf16)
// ============================================================================
__device__ __constant__ float c_sg[64] = {
    1, 1, 1, 1, 1, 1, 1, 1,
    1, 1, 1, 1, 1, 1, 1, 1,
    1,-1, 1, 1,-1,-1, 1,-1,
    1,-1,-1, 1, 1,-1,-1, 1,
    1,-1, 1, 1,-1,-1, 1,-1,
    1,-1,-1, 1, 1,-1,-1, 1,
    1, 1,-1, 1,-1, 1,-1,-1,
    1, 1,-1, 1,-1, 1,-1,-1};

__global__ void __launch_bounds__(256) kA(const float* __restrict__ x,
                                          const float* __restrict__ iw,
                                          const float* __restrict__ gg,
                                          const float* __restrict__ lnw,
                                          const float* __restrict__ lnb) {
    __shared__ float xs[8 * 256];
    __shared__ float cf[64];
    int tok = blockIdx.x, t = threadIdx.x;

    const float4* xsrc = (const float4*)(x + (size_t)tok * 2048);
    float4* xd = (float4*)xs;
    xd[t]       = xsrc[t];
    xd[t + 256] = xsrc[t + 256];
    if (t < 64) cf[t] = c_sg[t] / (1.f + __expf(-iw[t]));
    __syncthreads();

    float g = 1.f / (1.f + __expf(-gg[0]));
    float xr[8];
#pragma unroll
    for (int b = 0; b < 8; b++) xr[b] = xs[b * 256 + t];

    // Cayley targets (Cl(3)) — verified vs reference _derive_cayley_table
    constexpr int KTK[64] = {
        0,1,2,3,4,5,6,7,
        1,0,4,5,2,3,7,6,
        2,4,0,6,1,7,3,5,
        3,5,6,0,7,1,2,4,
        4,2,1,7,0,6,5,3,
        5,3,7,1,6,0,4,2,
        6,7,3,2,5,4,0,1,
        7,6,5,4,3,2,1,0};

    float geo[8] = {0, 0, 0, 0, 0, 0, 0, 0};
#pragma unroll
    for (int p = 0; p < 64; p++)
        geo[KTK[p]] += cf[p] * xr[p >> 3] * xr[p & 7];

#pragma unroll
    for (int b = 0; b < 8; b++)
        xs[b * 256 + t] = g * geo[b] + (1.f - g) * xr[b];
    __syncthreads();

    // LayerNorm: warp w handles blade b = w
    int w = t >> 5, lane = t & 31;
    float v[8], s = 0.f, sq = 0.f;
#pragma unroll
    for (int j = 0; j < 8; j++) {
        v[j] = xs[w * 256 + lane + 32 * j];
        s += v[j]; sq += v[j] * v[j];
    }
#pragma unroll
    for (int o = 16; o > 0; o >>= 1) {
        s  += __shfl_xor_sync(0xFFFFFFFFu, s, o);
        sq += __shfl_xor_sync(0xFFFFFFFFu, sq, o);
    }
    float mu   = s * (1.f / 256.f);
    float var  = fmaxf(sq * (1.f / 256.f) - mu * mu, 0.f);
    float rstd = rsqrtf(var + 1e-5f);

    size_t row = (size_t)tok * 8 + w;
    __nv_bfloat16* dst = g_flat + row * 256;
#pragma unroll
    for (int j = 0; j < 8; j++) {
        int col = lane + 32 * j;
        dst[col] = __float2bfloat16((v[j] - mu) * rstd * lnw[col] + lnb[col]);
    }
}

// ============================================================================
// HMMA GEMM common: CTA 128(M) x 128(N-rows of B), 8 warps (4M x 2N),
// warp tile 32x64, K-chunk 64, 3-stage cp.async pipeline, 1 sync/chunk.
// smem: per stage A 16KB @ s*16K, B 16KB @ 48K + s*16K. Total 96KB.
// 2 CTAs/SM (regs capped at 128) -> 16 warps/SM.
// ============================================================================
static constexpr int G_SMEM_BYTES = 98304;
static constexpr uint32_t BOFF = 49152;

// compute one K=64 chunk: c[2][8][4] accumulators (warp 32x64)
__device__ __forceinline__ void compute_chunk(uint32_t sA, uint32_t sB,
                                              int wm, int wn, int lane,
                                              float c[2][8][4]) {
#pragma unroll
    for (int ks = 0; ks < 4; ks++) {
        uint32_t a[2][4], b[4][4];
        int kb = ks * 32;                       // byte offset of k within 128B row
        int acol = (lane >> 4) * 16 + kb;
#pragma unroll
        for (int mt = 0; mt < 2; mt++) {
            uint32_t row = wm * 32 + mt * 16 + (lane & 15);
            LDSM_X4(a[mt], sA + swz(row * 128 + acol));
        }
        int bcol = ((lane >> 3) & 1) * 16 + kb;
#pragma unroll
        for (int p = 0; p < 4; p++) {
            uint32_t row = wn * 64 + p * 16 + (lane & 7) + ((lane >> 4) << 3);
            LDSM_X4(b[p], sB + swz(row * 128 + bcol));
        }
#pragma unroll
        for (int mt = 0; mt < 2; mt++)
#pragma unroll
            for (int nt = 0; nt < 8; nt++)
                MMA16816(c[mt][nt], a[mt], b[nt >> 1][(nt & 1) * 2], b[nt >> 1][(nt & 1) * 2 + 1]);
    }
}

// stage loader: A 128 rows x 64 bf16, B 128 rows x 64 bf16 at K-offset k0
__device__ __forceinline__ void load_chunk(uint32_t sA, uint32_t sB,
                                           const __nv_bfloat16* gA, int a_stride,
                                           const __nv_bfloat16* gB, int b_stride,
                                           int m0, int nb0, int k0, int t) {
#pragma unroll
    for (int i = 0; i < 4; i++) {               // A,B: 1024 x 16B each
        int u = t + i * 256;
        int r = u >> 3, cu = u & 7;
        uint32_t off = swz((uint32_t)r * 128 + cu * 16);
        CP_ASYNC16(sA + off, gA + (size_t)(m0 + r) * a_stride + k0 + cu * 8);
        CP_ASYNC16(sB + off, gB + (size_t)(nb0 + r) * b_stride + k0 + cu * 8);
    }
}

// ============================================================================
// GEMM1: g_flat[65536,256] @ g_B1 (gate/up interleaved) -> swiglu -> g_h
// grid (16, 512): x = n-block (fastest -> L2 A-tile reuse), y = m-block
// ============================================================================
__global__ void __launch_bounds__(256, 2) kGemm1() {
    extern __shared__ __align__(1024) char smem[];
    uint32_t sb = smem_to_u32(smem);
    int t = threadIdx.x, lane = t & 31, wid = t >> 5;
    int wm = wid & 3, wn = wid >> 2;
    int nb0 = blockIdx.x * 128, m0 = blockIdx.y * 128;

    float c[2][8][4] = {};
    load_chunk(sb,         sb + BOFF,         g_flat, 256, g_B1, 256, m0, nb0, 0,  t);
    CP_COMMIT();
    load_chunk(sb + 16384, sb + BOFF + 16384, g_flat, 256, g_B1, 256, m0, nb0, 64, t);
    CP_COMMIT();

#pragma unroll
    for (int kc = 0; kc < 4; kc++) {
        if (kc == 3) { CP_WAIT(0); } else { CP_WAIT(1); }
        __syncthreads();
        if (kc + 2 < 4) {
            int s = (kc + 2) % 3;
            load_chunk(sb + s * 16384, sb + BOFF + s * 16384,
                       g_flat, 256, g_B1, 256, m0, nb0, (kc + 2) * 64, t);
            CP_COMMIT();
        }
        int s = kc % 3;
        compute_chunk(sb + s * 16384, sb + BOFF + s * 16384, wm, wn, lane, c);
    }

    // epilogue: ntile 2q = gate, 2q+1 = up (same FFN cols) -> silu(g)*u, bf16
    int ncolw = blockIdx.x * 64 + wn * 32;
#pragma unroll
    for (int mt = 0; mt < 2; mt++) {
        int r0 = m0 + wm * 32 + mt * 16 + (lane >> 2);
#pragma unroll
        for (int q = 0; q < 4; q++) {
            float* cg = c[mt][2 * q];
            float* cu = c[mt][2 * q + 1];
            int ncol = ncolw + q * 8 + (lane & 3) * 2;
#pragma unroll
            for (int half = 0; half < 2; half++) {
                float zg0 = cg[half * 2], zg1 = cg[half * 2 + 1];
                float zu0 = cu[half * 2], zu1 = cu[half * 2 + 1];
                __nv_bfloat162 pk;
                pk.x = __float2bfloat16(zg0 / (1.f + __expf(-zg0)) * zu0);
                pk.y = __float2bfloat16(zg1 / (1.f + __expf(-zg1)) * zu1);
                *(__nv_bfloat162*)(g_h + (size_t)(r0 + half * 8) * 1024 + ncol) = pk;
            }
        }
    }
}

// ============================================================================
// GEMM2: g_h[65536,1024] @ g_B2[256,1024] -> + x residual -> out fp32
// grid (2, 512): x = n-block, y = m-block; K in 16 chunks of 64
// ============================================================================
__global__ void __launch_bounds__(256, 2)
kGemm2(const float* __restrict__ x, float* __restrict__ out) {
    extern __shared__ __align__(1024) char smem[];
    uint32_t sb = smem_to_u32(smem);
    int t = threadIdx.x, lane = t & 31, wid = t >> 5;
    int wm = wid & 3, wn = wid >> 2;
    int nb0 = blockIdx.x * 128, m0 = blockIdx.y * 128;

    float c[2][8][4] = {};
    load_chunk(sb,         sb + BOFF,         g_h, 1024, g_B2, 1024, m0, nb0, 0,  t);
    CP_COMMIT();
    load_chunk(sb + 16384, sb + BOFF + 16384, g_h, 1024, g_B2, 1024, m0, nb0, 64, t);
    CP_COMMIT();

    for (int kc = 0; kc < 16; kc++) {
        if (kc == 15) { CP_WAIT(0); } else { CP_WAIT(1); }
        __syncthreads();
        if (kc + 2 < 16) {
            int s = (kc + 2) % 3;
            load_chunk(sb + s * 16384, sb + BOFF + s * 16384,
                       g_h, 1024, g_B2, 1024, m0, nb0, (kc + 2) * 64, t);
            CP_COMMIT();
        }
        int s = kc % 3;
        compute_chunk(sb + s * 16384, sb + BOFF + s * 16384, wm, wn, lane, c);
    }

    // epilogue: fp32 residual add
#pragma unroll
    for (int mt = 0; mt < 2; mt++) {
        int r0 = m0 + wm * 32 + mt * 16 + (lane >> 2);
#pragma unroll
        for (int nt = 0; nt < 8; nt++) {
            int col = nb0 + wn * 64 + nt * 8 + (lane & 3) * 2;
#pragma unroll
            for (int half = 0; half < 2; half++) {
                size_t idx = (size_t)(r0 + half * 8) * 256 + col;
                float2 xv = *(const float2*)(x + idx);
                float2 ov;
                ov.x = xv.x + c[mt][nt][half * 2];
                ov.y = xv.y + c[mt][nt][half * 2 + 1];
                *(float2*)(out + idx) = ov;
            }
        }
    }
}

// ============================================================================
// Launch
// ============================================================================
extern "C" void kernel_launch(void* const* d_in, const int* in_sizes, int n_in,
                              void* d_out, int out_size) {
    (void)in_sizes; (void)n_in; (void)out_size;
    const float* x   = (const float*)d_in[0];
    const float* iw  = (const float*)d_in[1];
    const float* gg  = (const float*)d_in[2];
    const float* lnw = (const float*)d_in[3];
    const float* lnb = (const float*)d_in[4];
    const float* Wg  = (const float*)d_in[5];
    const float* Wu  = (const float*)d_in[6];
    const float* Wd  = (const float*)d_in[7];
    float* out = (float*)d_out;

    cudaFuncSetAttribute(kGemm1, cudaFuncAttributeMaxDynamicSharedMemorySize, G_SMEM_BYTES);
    cudaFuncSetAttribute(kGemm2, cudaFuncAttributeMaxDynamicSharedMemorySize, G_SMEM_BYTES);

    kPrep<<<3072, 256>>>(Wg, Wu, Wd);
    kA<<<NTOK, 256>>>(x, iw, gg, lnw, lnb);
    // n-grid = (2*DF)/128 interleaved B-rows per CTA  (R4 bug: was /256)
    kGemm1<<<dim3(2 * DF / 128, NROW / 128), 256, G_SMEM_BYTES>>>();
    kGemm2<<<dim3(DB / 128, NROW / 128), 256, G_SMEM_BYTES>>>(x, out);
}